// round 13
// baseline (speedup 1.0000x reference)
#include <cuda_runtime.h>
#include <cuda_fp16.h>
#include <mma.h>
#include <cstdint>

using namespace nvcuda;

// Fixed shapes
#define B_      2
#define L_      512
#define D_      256
#define TILE    32
#define THREADS 256
#define SST     264                      // fp16 row stride: 256 + 8 pad
#define TEL     (TILE * SST)
#define SMEM_BYTES (2 * TEL * 2)         // 33792 B -> 3+ CTAs/SM co-resident

// out[b,i,j] = sum_d x[b,i,d]*w1[d]*x[b,j,d] + bias   (symmetric)
// (lin_i - lin_j cancels under (P+P^T)/2; w2 = W[D:,0] dead.)
// fp16 single product, f32 accumulate: rel err ~3e-4 < 1e-3 (measured R11/12).

__device__ __forceinline__ uint32_t h2(float a, float b) {
    __half2 h = __floats2half2_rn(a, b);
    return *reinterpret_cast<uint32_t*>(&h);
}
__device__ __forceinline__ uint4 pack8(float4 f0, float4 f1) {
    uint4 v;
    v.x = h2(f0.x, f0.y);
    v.y = h2(f0.z, f0.w);
    v.z = h2(f1.x, f1.y);
    v.w = h2(f1.z, f1.w);
    return v;
}
__device__ __forceinline__ float4 mul4(float4 a, float4 w) {
    a.x *= w.x; a.y *= w.y; a.z *= w.z; a.w *= w.w;
    return a;
}

__global__ __launch_bounds__(THREADS, 3)
void fused_pairwise_kernel(const float* __restrict__ x,
                           const float* __restrict__ W,
                           const float* __restrict__ bias_p,
                           float* __restrict__ out) {
    extern __shared__ __align__(16) __half smem[];
    __half* sB = smem;            // fp16(x), j-strip (32 rows)
    __half* sA = smem + TEL;      // fp16(x*w1), i-strip (32 rows)

    const int bz  = blockIdx.z;
    const int ti  = blockIdx.y;
    const int tj  = blockIdx.x;
    const int tid = threadIdx.x;
    const int warp = tid >> 5;

    const float bias = __ldg(bias_p);

    const float4* A4 = (const float4*)(x + (size_t)(bz * L_ + ti * TILE) * D_);
    const float4* B4 = (const float4*)(x + (size_t)(bz * L_ + tj * TILE) * D_);
    const float4* W4 = (const float4*)W;   // w1 = W[:256]

    // ---- front end: threads 0-127 -> B strip, 128-255 -> A strip ----
    // column-strip mapping: each thread owns 2 f4 cols x 8 rows
    {
        const int g    = tid >> 7;          // 0 -> B, 1 -> A
        const int u    = tid & 127;
        const int pcol = u & 31;            // 0..31 (pairs of f4 cols)
        const int rblk = u >> 5;            // 0..3  (8 rows each)
        const int cf4  = pcol * 2;
        const float4* S = g ? A4 : B4;
        __half* dst = g ? sA : sB;
        float4 w0, w1;
        if (g) { w0 = __ldg(&W4[cf4]); w1 = __ldg(&W4[cf4 + 1]); }

        #pragma unroll
        for (int p = 0; p < 8; p++) {
            int row = rblk * 8 + p;
            float4 f0 = S[row * 64 + cf4];
            float4 f1 = S[row * 64 + cf4 + 1];
            if (g) { f0 = mul4(f0, w0); f1 = mul4(f1, w1); }
            *(uint4*)&dst[row * SST + cf4 * 4] = pack8(f0, f1);
        }
    }
    __syncthreads();

    // ---- MMA: warps 0-3, each a 16x16 quadrant, full K=256 ----
    if (warp >= 4) return;

    const int wr = (warp >> 1) & 1;
    const int wc = warp & 1;

    wmma::fragment<wmma::accumulator, 16, 16, 16, float> acc;
    wmma::fill_fragment(acc, 0.0f);

    const __half* Ab = sA + (wr * 16) * SST;
    const __half* Bb = sB + (wc * 16) * SST;

    #pragma unroll
    for (int kk = 0; kk < D_; kk += 16) {
        wmma::fragment<wmma::matrix_a, 16, 16, 16, __half, wmma::row_major> af;
        wmma::fragment<wmma::matrix_b, 16, 16, 16, __half, wmma::col_major> bf;
        wmma::load_matrix_sync(af, Ab + kk, SST);
        wmma::load_matrix_sync(bf, Bb + kk, SST);
        wmma::mma_sync(acc, af, bf, acc);
    }

    #pragma unroll
    for (int t = 0; t < acc.num_elements; t++)
        acc.x[t] += bias;
    int gi = ti * TILE + wr * 16;
    int gj = tj * TILE + wc * 16;
    float* dst = out + (size_t)bz * L_ * L_ + (size_t)gi * L_ + gj;
    wmma::store_matrix_sync(dst, acc, L_, wmma::mem_row_major);
}

// ---------------------------------------------------------------------------
// d_in[0] = inputs f32 (2,512,256), d_in[1] = W f32 (512,1), d_in[2] = b f32 (1,)
// d_out   = f32 (2,512,512,1)
// ---------------------------------------------------------------------------
extern "C" void kernel_launch(void* const* d_in, const int* in_sizes, int n_in,
                              void* d_out, int out_size) {
    const float* x    = (const float*)d_in[0];
    const float* W    = (const float*)d_in[1];
    const float* bptr = (const float*)d_in[2];
    float* out = (float*)d_out;

    static bool attr_set = false;
    if (!attr_set) {
        cudaFuncSetAttribute(fused_pairwise_kernel,
                             cudaFuncAttributeMaxDynamicSharedMemorySize, SMEM_BYTES);
        attr_set = true;
    }

    dim3 grid(L_ / TILE, L_ / TILE, B_);   // (16, 16, 2) = 512 CTAs, ~3.5/SM
    fused_pairwise_kernel<<<grid, THREADS, SMEM_BYTES>>>(x, W, bptr, out);
}